// round 6
// baseline (speedup 1.0000x reference)
#include <cuda_runtime.h>

// GAE backward scan, (B=8192, T=256, A=4), fp32.
//   c_t = gamma*lambda*nd_t ; d_t = r_t + gamma*nv_t*nd_t - v_t
//   gae_t = d_t + c_t*gae_{t+1}  (gae_T = 0);  adv = gae, ret = gae + v.
// Output: [adv (B*T*A) | ret (B*T*A)].
//
// R6: two batches per warp + depth-2 register pipeline -> 16 LDG.128 (8 KB)
//     in flight per warp, 2x scan ILP. Default-cached reads (exploit cross-
//     replay L2 residency), streaming stores. Warp affine scan retained.

#define GAMMA_F 0.99f
#define GL_F    (0.99f * 0.95f)

constexpr int B     = 8192;
constexpr int T     = 256;
constexpr int A     = 4;
constexpr int ROW4  = T * A / 4;    // 256 float4 per batch row
constexpr int BPW   = 2;            // batches per warp
constexpr int WPB   = 4;            // warps per block
constexpr int THREADS = 32 * WPB;
constexpr int ROUNDS  = T / 32;     // 8

struct Chunk { float4 r[BPW], tm[BPW], v[BPW], nv[BPW]; };

__device__ __forceinline__ Chunk ld_round(const float4* __restrict__ reward,
                                          const float4* __restrict__ term,
                                          const float4* __restrict__ value,
                                          const float4* __restrict__ nxtval,
                                          const int gbase[BPW], int off)
{
    Chunk c;
    #pragma unroll
    for (int i = 0; i < BPW; i++) {
        const int g = gbase[i] + off;
        c.r[i]  = reward[g];
        c.tm[i] = term[g];
        c.v[i]  = value[g];
        c.nv[i] = nxtval[g];
    }
    return c;
}

__global__ __launch_bounds__(THREADS)
void gae_kernel(const float4* __restrict__ reward,
                const float4* __restrict__ term,
                const float4* __restrict__ value,
                const float4* __restrict__ nxtval,
                float4* __restrict__ adv_out,
                float4* __restrict__ ret_out)
{
    const int lane = threadIdx.x & 31;
    const int warp = threadIdx.x >> 5;
    const int b0   = (blockIdx.x * WPB + warp) * BPW;

    int gbase[BPW];
    #pragma unroll
    for (int i = 0; i < BPW; i++)
        gbase[i] = (b0 + i) * ROW4 + lane;

    float carry[BPW][4];
    #pragma unroll
    for (int i = 0; i < BPW; i++)
        #pragma unroll
        for (int j = 0; j < 4; j++)
            carry[i][j] = 0.f;

    // depth-2 prologue: rounds 7 and 6 in flight
    Chunk buf[2];
    buf[(ROUNDS - 1) & 1] = ld_round(reward, term, value, nxtval, gbase, 32 * (ROUNDS - 1));
    buf[(ROUNDS - 2) & 1] = ld_round(reward, term, value, nxtval, gbase, 32 * (ROUNDS - 2));

    #pragma unroll
    for (int k = ROUNDS - 1; k >= 0; k--) {
        const int s = k & 1;
        const Chunk cur = buf[s];

        // refill this slot two rounds ahead
        if (k >= 2)
            buf[s] = ld_round(reward, term, value, nxtval, gbase, 32 * (k - 2));

        #pragma unroll
        for (int i = 0; i < BPW; i++) {
            const float* rp = &cur.r[i].x;
            const float* tp = &cur.tm[i].x;
            const float* vp = &cur.v[i].x;
            const float* np = &cur.nv[i].x;
            float gae[4];

            #pragma unroll
            for (int j = 0; j < 4; j++) {
                const float nd = 1.0f - tp[j];
                float Sc  = GL_F * nd;                                 // c_t
                float Off = fmaf(GAMMA_F * np[j], nd, rp[j]) - vp[j];  // d_t

                // backward inclusive affine scan over lanes
                #pragma unroll
                for (int o = 1; o < 32; o <<= 1) {
                    const float ScU  = __shfl_down_sync(0xffffffffu, Sc,  o);
                    const float OffU = __shfl_down_sync(0xffffffffu, Off, o);
                    if (lane + o < 32) {
                        Off = fmaf(Sc, OffU, Off);
                        Sc *= ScU;
                    }
                }
                gae[j]      = fmaf(Sc, carry[i][j], Off);
                carry[i][j] = __shfl_sync(0xffffffffu, gae[j], 0);  // gae at t=32k
            }

            const int go = gbase[i] + 32 * k;
            float4 ad, rt;
            ad.x = gae[0]; ad.y = gae[1]; ad.z = gae[2]; ad.w = gae[3];
            rt.x = gae[0] + vp[0]; rt.y = gae[1] + vp[1];
            rt.z = gae[2] + vp[2]; rt.w = gae[3] + vp[3];
            __stcs(adv_out + go, ad);
            __stcs(ret_out + go, rt);
        }
    }
}

extern "C" void kernel_launch(void* const* d_in, const int* in_sizes, int n_in,
                              void* d_out, int out_size)
{
    const float4* reward = (const float4*)d_in[0];
    const float4* term   = (const float4*)d_in[1];
    const float4* value  = (const float4*)d_in[2];
    const float4* nxtval = (const float4*)d_in[3];

    float* out = (float*)d_out;
    float4* adv = (float4*)out;
    float4* ret = (float4*)(out + (size_t)B * T * A);

    gae_kernel<<<B / (WPB * BPW), THREADS>>>(reward, term, value, nxtval, adv, ret);
}

// round 7
// speedup vs baseline: 1.0489x; 1.0489x over previous
#include <cuda_runtime.h>

// GAE backward scan, (B=8192, T=256, A=4), fp32.
//   c_t = gamma*lambda*nd_t ; d_t = r_t + gamma*nv_t*nd_t - v_t
//   gae_t = d_t + c_t*gae_{t+1}  (gae_T = 0);  adv = gae, ret = gae + v.
// Output: [adv (B*T*A) | ret (B*T*A)].
//
// R7: R5 (best) with pipeline depth 2 -> 3 as the single change.
//     Three named Chunk buffers, fully unrolled rounds (static rotation) so
//     ptxas keeps 12 LDG.128 in flight. __ldcs reads / __stcs writes kept.

#define GAMMA_F 0.99f
#define GL_F    (0.99f * 0.95f)

constexpr int B     = 8192;
constexpr int T     = 256;
constexpr int A     = 4;
constexpr int ROW4  = T * A / 4;    // 256 float4 per batch row
constexpr int WPB   = 4;            // independent warps per block
constexpr int THREADS = 32 * WPB;
constexpr int ROUNDS  = T / 32;     // 8
constexpr int DEPTH   = 3;

struct Chunk { float4 r, tm, v, nv; };

__device__ __forceinline__ Chunk ld_round(const float4* __restrict__ reward,
                                          const float4* __restrict__ term,
                                          const float4* __restrict__ value,
                                          const float4* __restrict__ nxtval,
                                          int g)
{
    Chunk c;
    c.r  = __ldcs(reward + g);
    c.tm = __ldcs(term   + g);
    c.v  = __ldcs(value  + g);
    c.nv = __ldcs(nxtval + g);
    return c;
}

__global__ __launch_bounds__(THREADS)
void gae_kernel(const float4* __restrict__ reward,
                const float4* __restrict__ term,
                const float4* __restrict__ value,
                const float4* __restrict__ nxtval,
                float4* __restrict__ adv_out,
                float4* __restrict__ ret_out)
{
    const int lane = threadIdx.x & 31;
    const int warp = threadIdx.x >> 5;
    const int b    = blockIdx.x * WPB + warp;
    const int base = b * ROW4 + lane;

    float carry[4] = {0.f, 0.f, 0.f, 0.f};

    // depth-3 prologue: rounds 7, 6, 5 in flight
    Chunk buf0 = ld_round(reward, term, value, nxtval, base + 32 * (ROUNDS - 1));
    Chunk buf1 = ld_round(reward, term, value, nxtval, base + 32 * (ROUNDS - 2));
    Chunk buf2 = ld_round(reward, term, value, nxtval, base + 32 * (ROUNDS - 3));

    #pragma unroll
    for (int k = ROUNDS - 1; k >= 0; k--) {
        // static rotation: iteration (ROUNDS-1-k) uses buf (ROUNDS-1-k) % 3
        const int slot = (ROUNDS - 1 - k) % DEPTH;
        const Chunk cur = (slot == 0) ? buf0 : (slot == 1) ? buf1 : buf2;

        // refill this slot DEPTH rounds ahead; latency spans three scans
        if (k >= DEPTH) {
            const Chunk nw = ld_round(reward, term, value, nxtval,
                                      base + 32 * (k - DEPTH));
            if      (slot == 0) buf0 = nw;
            else if (slot == 1) buf1 = nw;
            else                buf2 = nw;
        }

        const float* rp = &cur.r.x;
        const float* tp = &cur.tm.x;
        const float* vp = &cur.v.x;
        const float* np = &cur.nv.x;
        float gae[4];

        #pragma unroll
        for (int j = 0; j < 4; j++) {
            const float nd = 1.0f - tp[j];
            float Sc  = GL_F * nd;                                 // c_t
            float Off = fmaf(GAMMA_F * np[j], nd, rp[j]) - vp[j];  // d_t

            // backward inclusive affine scan over lanes
            #pragma unroll
            for (int o = 1; o < 32; o <<= 1) {
                const float ScU  = __shfl_down_sync(0xffffffffu, Sc,  o);
                const float OffU = __shfl_down_sync(0xffffffffu, Off, o);
                if (lane + o < 32) {
                    Off = fmaf(Sc, OffU, Off);
                    Sc *= ScU;
                }
            }
            gae[j]   = fmaf(Sc, carry[j], Off);
            carry[j] = __shfl_sync(0xffffffffu, gae[j], 0);  // gae at t = 32k
        }

        const int go = base + 32 * k;
        float4 ad, rt;
        ad.x = gae[0]; ad.y = gae[1]; ad.z = gae[2]; ad.w = gae[3];
        rt.x = gae[0] + vp[0]; rt.y = gae[1] + vp[1];
        rt.z = gae[2] + vp[2]; rt.w = gae[3] + vp[3];
        __stcs(adv_out + go, ad);
        __stcs(ret_out + go, rt);
    }
}

extern "C" void kernel_launch(void* const* d_in, const int* in_sizes, int n_in,
                              void* d_out, int out_size)
{
    const float4* reward = (const float4*)d_in[0];
    const float4* term   = (const float4*)d_in[1];
    const float4* value  = (const float4*)d_in[2];
    const float4* nxtval = (const float4*)d_in[3];

    float* out = (float*)d_out;
    float4* adv = (float4*)out;
    float4* ret = (float4*)(out + (size_t)B * T * A);

    gae_kernel<<<B / WPB, THREADS>>>(reward, term, value, nxtval, adv, ret);
}